// round 1
// baseline (speedup 1.0000x reference)
#include <cuda_runtime.h>

#define BB     32
#define IDF    64
#define RES    128
#define QL     (RES*RES)      // 16384
#define CDF    768
#define SL     18
#define ADIM   100
#define NSPLIT 128
#define KCH    (QL/NSPLIT)    // 128

// Scratch (no cudaMalloc allowed)
__device__ float g_sourceT[BB*IDF*SL];        // [b][i][s]
__device__ float g_wctx2[BB*QL];              // [b][q]
__device__ float g_partial[NSPLIT*ADIM*BB];   // [split][a][b]

__device__ __forceinline__ unsigned long long pack2(float lo, float hi){
    unsigned long long r;
    asm("mov.b64 %0, {%1,%2};" : "=l"(r) : "f"(lo), "f"(hi));
    return r;
}
__device__ __forceinline__ void unpack2(unsigned long long v, float &lo, float &hi){
    asm("mov.b64 {%0,%1}, %2;" : "=f"(lo), "=f"(hi) : "l"(v));
}
// d = a*b + d  (packed 2x fp32, sm_100+ FFMA2)
__device__ __forceinline__ void ffma2(unsigned long long &d, unsigned long long a, unsigned long long b){
    asm("fma.rn.f32x2 %0, %1, %2, %0;" : "+l"(d) : "l"(a), "l"(b));
}

// ---------------------------------------------------------------------------
// k1: sourceT[b,i,s] = sum_c conv_ctx_w[i,c] * context[b,c,s]
// grid (4, 32): 16 i-rows per block, one batch per blockIdx.y. 288 threads.
// ---------------------------------------------------------------------------
__global__ void __launch_bounds__(288) k1_sourceT(const float* __restrict__ ctx,
                                                  const float* __restrict__ w){
    const int b   = blockIdx.y;
    const int tid = threadIdx.x;
    const int s   = tid % SL;
    const int i   = blockIdx.x * 16 + tid / SL;   // tid/SL in [0,16)

    __shared__ float sctx[256*SL];                // 18 KB chunk of context[b]
    float acc = 0.f;
    for (int c0 = 0; c0 < CDF; c0 += 256){
        __syncthreads();
        // context[b] chunk is contiguous (c-major, s minor): straight copy
        for (int idx = tid; idx < 256*SL; idx += 288)
            sctx[idx] = ctx[b*CDF*SL + c0*SL + idx];
        __syncthreads();
        const float* wr = w + i*CDF + c0;
        #pragma unroll 8
        for (int c = 0; c < 256; ++c)
            acc = fmaf(__ldg(wr + c), sctx[c*SL + s], acc);
    }
    g_sourceT[b*IDF*SL + i*SL + s] = acc;
}

// ---------------------------------------------------------------------------
// k2: fused scores GEMV + softmax + cs-dot. Each thread owns 2 queries
// (packed f32x2). grid (32 qtiles, 32 batches), 256 threads -> 512 q/block.
// ---------------------------------------------------------------------------
__global__ void __launch_bounds__(256) k2_attn(const float* __restrict__ x,
                                               const float* __restrict__ conv_w,
                                               const float* __restrict__ conv_b){
    const int b   = blockIdx.y;
    const int tid = threadIdx.x;

    __shared__ __align__(16) unsigned long long sdup[IDF*SL];  // sourceT duplicated (v,v)
    __shared__ float scs[SL];                                   // cs[b,s]

    for (int idx = tid; idx < IDF*SL; idx += 256){
        float v = g_sourceT[b*IDF*SL + idx];
        sdup[idx] = pack2(v, v);
    }
    __syncthreads();
    if (tid < SL){
        float c = 0.f;
        #pragma unroll 8
        for (int i = 0; i < IDF; ++i){
            float lo, hi; unpack2(sdup[i*SL + tid], lo, hi);
            c = fmaf(__ldg(conv_w + i), lo, c);
        }
        scs[tid] = c;
    }
    __syncthreads();

    const int q0 = blockIdx.x * 512 + tid * 2;
    const float* xp = x + ((long long)b*IDF)*QL + q0;

    unsigned long long sc[SL];
    #pragma unroll
    for (int s = 0; s < SL; ++s) sc[s] = 0ULL;    // (0.0f,0.0f)

    #pragma unroll 4
    for (int i = 0; i < IDF; ++i){
        unsigned long long t =
            *reinterpret_cast<const unsigned long long*>(xp + (long long)i*QL);
        const ulonglong2* row = reinterpret_cast<const ulonglong2*>(&sdup[i*SL]);
        #pragma unroll
        for (int p = 0; p < SL/2; ++p){
            ulonglong2 rv = row[p];               // LDS.128: two duplicated pairs
            ffma2(sc[2*p+0], t, rv.x);
            ffma2(sc[2*p+1], t, rv.y);
        }
    }

    // unpack (free: b64 reg = 2 fp32 regs)
    float sa[SL], sb[SL];
    #pragma unroll
    for (int s = 0; s < SL; ++s) unpack2(sc[s], sa[s], sb[s]);

    float csr[SL];
    #pragma unroll
    for (int s = 0; s < SL; ++s) csr[s] = scs[s];

    float m0 = sa[0], m1 = sb[0];
    #pragma unroll
    for (int s = 1; s < SL; ++s){ m0 = fmaxf(m0, sa[s]); m1 = fmaxf(m1, sb[s]); }
    float d0 = 0.f, d1 = 0.f, n0 = 0.f, n1 = 0.f;
    #pragma unroll
    for (int s = 0; s < SL; ++s){
        float e0 = __expf(sa[s] - m0);
        float e1 = __expf(sb[s] - m1);
        d0 += e0; d1 += e1;
        n0 = fmaf(e0, csr[s], n0);
        n1 = fmaf(e1, csr[s], n1);
    }
    float cb = conv_b[0];
    float2 out2 = make_float2(n0/d0 + cb, n1/d1 + cb);
    *reinterpret_cast<float2*>(&g_wctx2[b*QL + q0]) = out2;
}

// ---------------------------------------------------------------------------
// k3: split-K FC partials. block = one K-chunk of 128. Warp handles columns
// a = w, w+8, ...; lane = batch index. Deterministic (no atomics).
// ---------------------------------------------------------------------------
__global__ void __launch_bounds__(256) k3_fc(const float* __restrict__ fcw){
    const int split = blockIdx.x;
    const int k0    = split * KCH;
    const int tid   = threadIdx.x;
    const int lane  = tid & 31;
    const int w     = tid >> 5;

    __shared__ float sm[KCH*33];   // [k][b], padded row 33 (conflict-free T)
    for (int idx = tid; idx < BB*KCH; idx += 256){
        int b = idx >> 7;          // /128
        int k = idx & 127;
        sm[k*33 + b] = g_wctx2[b*QL + k0 + k];
    }
    __syncthreads();

    for (int a = w; a < ADIM; a += 8){
        const float4* fp = reinterpret_cast<const float4*>(fcw + (long long)a*QL + k0);
        float acc = 0.f;
        #pragma unroll 8
        for (int kq = 0; kq < KCH/4; ++kq){
            float4 f = __ldg(fp + kq);
            int k = kq*4;
            acc = fmaf(f.x, sm[(k+0)*33 + lane], acc);
            acc = fmaf(f.y, sm[(k+1)*33 + lane], acc);
            acc = fmaf(f.z, sm[(k+2)*33 + lane], acc);
            acc = fmaf(f.w, sm[(k+3)*33 + lane], acc);
        }
        g_partial[split*(ADIM*BB) + a*BB + lane] = acc;
    }
}

// ---------------------------------------------------------------------------
// k4: reduce split partials, add fc_b. out[b*100+a].
// ---------------------------------------------------------------------------
__global__ void k4_reduce(const float* __restrict__ fcb, float* __restrict__ out){
    int idx = blockIdx.x * 256 + threadIdx.x;
    if (idx >= BB*ADIM) return;
    int b = idx / ADIM, a = idx % ADIM;
    float acc = fcb[a];
    #pragma unroll 8
    for (int sp = 0; sp < NSPLIT; ++sp)
        acc += g_partial[sp*(ADIM*BB) + a*BB + b];
    out[idx] = acc;
}

extern "C" void kernel_launch(void* const* d_in, const int* in_sizes, int n_in,
                              void* d_out, int out_size){
    const float* inputs     = (const float*)d_in[0];  // [32,64,128,128]
    const float* context    = (const float*)d_in[1];  // [32,768,18]
    const float* conv_ctx_w = (const float*)d_in[2];  // [64,768]
    const float* conv_w     = (const float*)d_in[3];  // [64]
    const float* conv_b     = (const float*)d_in[4];  // [1]
    const float* fc_w       = (const float*)d_in[5];  // [100,16384]
    const float* fc_b       = (const float*)d_in[6];  // [100]
    float* out = (float*)d_out;                        // [32,100]

    k1_sourceT<<<dim3(4, BB), 288>>>(context, conv_ctx_w);
    k2_attn   <<<dim3(QL/512, BB), 256>>>(inputs, conv_w, conv_b);
    k3_fc     <<<NSPLIT, 256>>>(fc_w);
    k4_reduce <<<(BB*ADIM + 255)/256, 256>>>(fc_b, out);
}

// round 2
// speedup vs baseline: 1.8092x; 1.8092x over previous
#include <cuda_runtime.h>

#define BB     32
#define IDF    64
#define RES    128
#define QL     (RES*RES)      // 16384
#define CDF    768
#define SL     18
#define ADIM   100
#define NSPLIT 128
#define KCH    (QL/NSPLIT)    // 128

// Scratch (no cudaMalloc allowed)
__device__ float g_sourceT[BB*IDF*SL];        // [b][i][s]
__device__ float g_wctx2[BB*QL];              // [b][q]
__device__ float g_partial[NSPLIT*ADIM*BB];   // [split][a][b]

__device__ __forceinline__ unsigned long long pack2(float lo, float hi){
    unsigned long long r;
    asm("mov.b64 %0, {%1,%2};" : "=l"(r) : "f"(lo), "f"(hi));
    return r;
}
__device__ __forceinline__ void unpack2(unsigned long long v, float &lo, float &hi){
    asm("mov.b64 {%0,%1}, %2;" : "=f"(lo), "=f"(hi) : "l"(v));
}
// d = a*b + d  (packed 2x fp32, sm_100+ FFMA2)
__device__ __forceinline__ void ffma2(unsigned long long &d, unsigned long long a, unsigned long long b){
    asm("fma.rn.f32x2 %0, %1, %2, %0;" : "+l"(d) : "l"(a), "l"(b));
}

// ---------------------------------------------------------------------------
// k1: sourceT[b,i,s] = sum_c conv_ctx_w[i,c] * context[b,c,s]
// warp-per-(b,i): grid (8 igroups, 32 b), 256 threads (8 warps = 8 i rows).
// ctx[b] staged through smem in 2 chunks of 384 c; lane owns c = lane+32j.
// ---------------------------------------------------------------------------
__global__ void __launch_bounds__(256) k1_sourceT(const float* __restrict__ ctx,
                                                  const float* __restrict__ w){
    const int b    = blockIdx.y;
    const int tid  = threadIdx.x;
    const int lane = tid & 31;
    const int i    = blockIdx.x * 8 + (tid >> 5);

    __shared__ float sctx[384*SL];     // 27 KB chunk of context[b]

    float acc[SL];
    #pragma unroll
    for (int s = 0; s < SL; ++s) acc[s] = 0.f;

    for (int c0 = 0; c0 < CDF; c0 += 384){
        __syncthreads();
        const float4* src = reinterpret_cast<const float4*>(ctx + (long long)b*CDF*SL + c0*SL);
        float4* dst = reinterpret_cast<float4*>(sctx);
        #pragma unroll
        for (int idx = tid; idx < 384*SL/4; idx += 256) dst[idx] = src[idx];
        __syncthreads();

        const float* wr = w + i*CDF + c0;
        #pragma unroll 4
        for (int j = 0; j < 12; ++j){
            const int c = lane + j*32;
            const float wv = __ldg(wr + c);
            const float* cp = &sctx[c*SL];
            #pragma unroll
            for (int s = 0; s < SL; ++s) acc[s] = fmaf(wv, cp[s], acc[s]);
        }
    }

    // butterfly reduce across lanes (c-partials)
    #pragma unroll
    for (int off = 16; off; off >>= 1){
        #pragma unroll
        for (int s = 0; s < SL; ++s)
            acc[s] += __shfl_xor_sync(0xffffffffu, acc[s], off);
    }
    if (lane == 0){
        #pragma unroll
        for (int s = 0; s < SL; ++s)
            g_sourceT[b*IDF*SL + i*SL + s] = acc[s];
    }
}

// ---------------------------------------------------------------------------
// k2: fused scores GEMV + softmax + cs-dot. Each thread owns 2 queries
// (packed f32x2). grid (32 qtiles, 32 batches), 256 threads -> 512 q/block.
// ---------------------------------------------------------------------------
__global__ void __launch_bounds__(256) k2_attn(const float* __restrict__ x,
                                               const float* __restrict__ conv_w,
                                               const float* __restrict__ conv_b){
    const int b   = blockIdx.y;
    const int tid = threadIdx.x;

    __shared__ __align__(16) unsigned long long sdup[IDF*SL];  // sourceT duplicated (v,v)
    __shared__ float scs[SL];                                   // cs[b,s]

    for (int idx = tid; idx < IDF*SL; idx += 256){
        float v = g_sourceT[b*IDF*SL + idx];
        sdup[idx] = pack2(v, v);
    }
    __syncthreads();
    if (tid < SL){
        float c = 0.f;
        #pragma unroll 8
        for (int i = 0; i < IDF; ++i){
            float lo, hi; unpack2(sdup[i*SL + tid], lo, hi);
            c = fmaf(__ldg(conv_w + i), lo, c);
        }
        scs[tid] = c;
    }
    __syncthreads();

    const int q0 = blockIdx.x * 512 + tid * 2;
    const float* xp = x + ((long long)b*IDF)*QL + q0;

    unsigned long long sc[SL];
    #pragma unroll
    for (int s = 0; s < SL; ++s) sc[s] = 0ULL;    // (0.0f,0.0f)

    #pragma unroll 8
    for (int i = 0; i < IDF; ++i){
        unsigned long long t =
            *reinterpret_cast<const unsigned long long*>(xp + (long long)i*QL);
        const ulonglong2* row = reinterpret_cast<const ulonglong2*>(&sdup[i*SL]);
        #pragma unroll
        for (int p = 0; p < SL/2; ++p){
            ulonglong2 rv = row[p];               // LDS.128: two duplicated pairs
            ffma2(sc[2*p+0], t, rv.x);
            ffma2(sc[2*p+1], t, rv.y);
        }
    }

    float sa[SL], sb[SL];
    #pragma unroll
    for (int s = 0; s < SL; ++s) unpack2(sc[s], sa[s], sb[s]);

    float csr[SL];
    #pragma unroll
    for (int s = 0; s < SL; ++s) csr[s] = scs[s];

    float m0 = sa[0], m1 = sb[0];
    #pragma unroll
    for (int s = 1; s < SL; ++s){ m0 = fmaxf(m0, sa[s]); m1 = fmaxf(m1, sb[s]); }
    float d0 = 0.f, d1 = 0.f, n0 = 0.f, n1 = 0.f;
    #pragma unroll
    for (int s = 0; s < SL; ++s){
        float e0 = __expf(sa[s] - m0);
        float e1 = __expf(sb[s] - m1);
        d0 += e0; d1 += e1;
        n0 = fmaf(e0, csr[s], n0);
        n1 = fmaf(e1, csr[s], n1);
    }
    float cb = conv_b[0];
    float2 out2 = make_float2(n0/d0 + cb, n1/d1 + cb);
    *reinterpret_cast<float2*>(&g_wctx2[b*QL + q0]) = out2;
}

// ---------------------------------------------------------------------------
// k3: split-K FC partials. grid (128 splits, 7 a-groups). Each warp handles
// an a-PAIR: one LDS feeds two FMAs, two independent LDG chains (2x MLP).
// lane = batch index. Deterministic (no atomics).
// ---------------------------------------------------------------------------
__global__ void __launch_bounds__(256) k3_fc(const float* __restrict__ fcw){
    const int split = blockIdx.x;
    const int k0    = split * KCH;
    const int tid   = threadIdx.x;
    const int lane  = tid & 31;
    const int w     = tid >> 5;

    __shared__ float sm[KCH*33];   // [k][b], padded row 33 (conflict-free T)
    for (int idx = tid; idx < BB*KCH; idx += 256){
        int b = idx >> 7;          // /128
        int k = idx & 127;
        sm[k*33 + b] = g_wctx2[b*QL + k0 + k];
    }
    __syncthreads();

    const int a0 = blockIdx.y * 16 + w * 2;   // a-pair {a0, a0+1}
    if (a0 >= ADIM) return;

    const float4* f0 = reinterpret_cast<const float4*>(fcw + (long long)(a0  )*QL + k0);
    const float4* f1 = reinterpret_cast<const float4*>(fcw + (long long)(a0+1)*QL + k0);
    float acc0 = 0.f, acc1 = 0.f;
    #pragma unroll 8
    for (int kq = 0; kq < KCH/4; ++kq){
        float4 x0 = __ldg(f0 + kq);
        float4 x1 = __ldg(f1 + kq);
        const int k = kq*4;
        float v0 = sm[(k+0)*33 + lane];
        float v1 = sm[(k+1)*33 + lane];
        float v2 = sm[(k+2)*33 + lane];
        float v3 = sm[(k+3)*33 + lane];
        acc0 = fmaf(x0.x, v0, acc0);  acc1 = fmaf(x1.x, v0, acc1);
        acc0 = fmaf(x0.y, v1, acc0);  acc1 = fmaf(x1.y, v1, acc1);
        acc0 = fmaf(x0.z, v2, acc0);  acc1 = fmaf(x1.z, v2, acc1);
        acc0 = fmaf(x0.w, v3, acc0);  acc1 = fmaf(x1.w, v3, acc1);
    }
    g_partial[split*(ADIM*BB) + (a0  )*BB + lane] = acc0;
    g_partial[split*(ADIM*BB) + (a0+1)*BB + lane] = acc1;
}

// ---------------------------------------------------------------------------
// k4: parallel reduce of split partials. One block per a-column; 8-way split
// over sp + smem tree. Coalesced 128B loads.
// ---------------------------------------------------------------------------
__global__ void __launch_bounds__(256) k4_reduce(const float* __restrict__ fcb,
                                                 float* __restrict__ out){
    const int a   = blockIdx.x;          // 0..99
    const int tid = threadIdx.x;
    const int b   = tid & 31;
    const int g   = tid >> 5;            // 0..7

    float acc = 0.f;
    #pragma unroll
    for (int sp = g; sp < NSPLIT; sp += 8)
        acc += g_partial[sp*(ADIM*BB) + a*BB + b];

    __shared__ float red[256];
    red[tid] = acc;
    __syncthreads();
    if (g == 0){
        float v = red[b] + red[b+32] + red[b+64] + red[b+96]
                + red[b+128] + red[b+160] + red[b+192] + red[b+224];
        out[b*ADIM + a] = v + fcb[a];
    }
}

extern "C" void kernel_launch(void* const* d_in, const int* in_sizes, int n_in,
                              void* d_out, int out_size){
    const float* inputs     = (const float*)d_in[0];  // [32,64,128,128]
    const float* context    = (const float*)d_in[1];  // [32,768,18]
    const float* conv_ctx_w = (const float*)d_in[2];  // [64,768]
    const float* conv_w     = (const float*)d_in[3];  // [64]
    const float* conv_b     = (const float*)d_in[4];  // [1]
    const float* fc_w       = (const float*)d_in[5];  // [100,16384]
    const float* fc_b       = (const float*)d_in[6];  // [100]
    float* out = (float*)d_out;                        // [32,100]

    k1_sourceT<<<dim3(8, BB), 256>>>(context, conv_ctx_w);
    k2_attn   <<<dim3(QL/512, BB), 256>>>(inputs, conv_w, conv_b);
    k3_fc     <<<dim3(NSPLIT, 7), 256>>>(fc_w);
    k4_reduce <<<ADIM, 256>>>(fc_b, out);
}

// round 3
// speedup vs baseline: 2.1512x; 1.1890x over previous
#include <cuda_runtime.h>

#define BB     32
#define IDF    64
#define RES    128
#define QL     (RES*RES)      // 16384
#define CDF    768
#define SL     18
#define ADIM   100
#define NSPLIT 64
#define KCH    (QL/NSPLIT)    // 256

// Scratch (no cudaMalloc allowed)
__device__ float g_sourceT[BB*IDF*SL];        // [b][i][s]
__device__ float g_wctx2[BB*QL];              // [b][q]
__device__ float g_partial[NSPLIT*ADIM*BB];   // [split][a][b]

__device__ __forceinline__ unsigned long long pack2(float lo, float hi){
    unsigned long long r;
    asm("mov.b64 %0, {%1,%2};" : "=l"(r) : "f"(lo), "f"(hi));
    return r;
}
__device__ __forceinline__ void unpack2(unsigned long long v, float &lo, float &hi){
    asm("mov.b64 {%0,%1}, %2;" : "=f"(lo), "=f"(hi) : "l"(v));
}
// d = a*b + d  (packed 2x fp32, sm_100+ FFMA2)
__device__ __forceinline__ void ffma2(unsigned long long &d, unsigned long long a, unsigned long long b){
    asm("fma.rn.f32x2 %0, %1, %2, %0;" : "+l"(d) : "l"(a), "l"(b));
}

// ---------------------------------------------------------------------------
// k1: sourceT[b,i,s] = sum_c conv_ctx_w[i,c] * context[b,c,s]
// warp-per-(b,i): grid (8 igroups, 32 b), 256 threads (8 warps = 8 i rows).
// ---------------------------------------------------------------------------
__global__ void __launch_bounds__(256) k1_sourceT(const float* __restrict__ ctx,
                                                  const float* __restrict__ w){
    const int b    = blockIdx.y;
    const int tid  = threadIdx.x;
    const int lane = tid & 31;
    const int i    = blockIdx.x * 8 + (tid >> 5);

    __shared__ float sctx[384*SL];     // 27 KB chunk of context[b]

    float acc[SL];
    #pragma unroll
    for (int s = 0; s < SL; ++s) acc[s] = 0.f;

    for (int c0 = 0; c0 < CDF; c0 += 384){
        __syncthreads();
        const float4* src = reinterpret_cast<const float4*>(ctx + (long long)b*CDF*SL + c0*SL);
        float4* dst = reinterpret_cast<float4*>(sctx);
        #pragma unroll
        for (int idx = tid; idx < 384*SL/4; idx += 256) dst[idx] = src[idx];
        __syncthreads();

        const float* wr = w + i*CDF + c0;
        #pragma unroll 4
        for (int j = 0; j < 12; ++j){
            const int c = lane + j*32;
            const float wv = __ldg(wr + c);
            const float* cp = &sctx[c*SL];
            #pragma unroll
            for (int s = 0; s < SL; ++s) acc[s] = fmaf(wv, cp[s], acc[s]);
        }
    }

    #pragma unroll
    for (int off = 16; off; off >>= 1){
        #pragma unroll
        for (int s = 0; s < SL; ++s)
            acc[s] += __shfl_xor_sync(0xffffffffu, acc[s], off);
    }
    if (lane == 0){
        #pragma unroll
        for (int s = 0; s < SL; ++s)
            g_sourceT[b*IDF*SL + i*SL + s] = acc[s];
    }
}

// ---------------------------------------------------------------------------
// k2: fused scores GEMV + softmax + cs-dot. Each thread owns 4 queries
// (2x f32x2 accumulator banks). grid (16 qtiles, 32 b), 256 thr -> 1024 q/blk.
// ---------------------------------------------------------------------------
__device__ __forceinline__ float2 k2_finish(const unsigned long long* sc,
                                            const float* scs, float cb){
    float sa[SL], sb[SL];
    #pragma unroll
    for (int s = 0; s < SL; ++s) unpack2(sc[s], sa[s], sb[s]);
    float m0 = sa[0], m1 = sb[0];
    #pragma unroll
    for (int s = 1; s < SL; ++s){ m0 = fmaxf(m0, sa[s]); m1 = fmaxf(m1, sb[s]); }
    float d0 = 0.f, d1 = 0.f, n0 = 0.f, n1 = 0.f;
    #pragma unroll
    for (int s = 0; s < SL; ++s){
        float e0 = __expf(sa[s] - m0);
        float e1 = __expf(sb[s] - m1);
        float c  = scs[s];               // broadcast LDS.32
        d0 += e0; d1 += e1;
        n0 = fmaf(e0, c, n0);
        n1 = fmaf(e1, c, n1);
    }
    return make_float2(n0/d0 + cb, n1/d1 + cb);
}

__global__ void __launch_bounds__(256, 2) k2_attn(const float* __restrict__ x,
                                                  const float* __restrict__ conv_w,
                                                  const float* __restrict__ conv_b){
    const int b   = blockIdx.y;
    const int tid = threadIdx.x;

    __shared__ __align__(16) unsigned long long sdup[IDF*SL];  // sourceT dup (v,v)
    __shared__ float scs[SL];                                   // cs[b,s]

    for (int idx = tid; idx < IDF*SL; idx += 256){
        float v = g_sourceT[b*IDF*SL + idx];
        sdup[idx] = pack2(v, v);
    }
    __syncthreads();
    if (tid < SL){
        float c = 0.f;
        #pragma unroll 8
        for (int i = 0; i < IDF; ++i){
            float lo, hi; unpack2(sdup[i*SL + tid], lo, hi);
            c = fmaf(__ldg(conv_w + i), lo, c);
        }
        scs[tid] = c;
    }
    __syncthreads();

    const int q0 = blockIdx.x * 1024 + tid * 4;
    const ulonglong2* xp =
        reinterpret_cast<const ulonglong2*>(x + ((long long)b*IDF)*QL + q0);

    unsigned long long sc0[SL], sc1[SL];
    #pragma unroll
    for (int s = 0; s < SL; ++s){ sc0[s] = 0ULL; sc1[s] = 0ULL; }

    #pragma unroll 4
    for (int i = 0; i < IDF; ++i){
        ulonglong2 t = *xp;                          // LDG.128: q0..q3
        xp += QL/4;                                  // next channel (QL floats)
        const ulonglong2* row = reinterpret_cast<const ulonglong2*>(&sdup[i*SL]);
        #pragma unroll
        for (int p = 0; p < SL/2; ++p){
            ulonglong2 rv = row[p];                  // two duplicated s-values
            ffma2(sc0[2*p+0], t.x, rv.x);
            ffma2(sc0[2*p+1], t.x, rv.y);
            ffma2(sc1[2*p+0], t.y, rv.x);
            ffma2(sc1[2*p+1], t.y, rv.y);
        }
    }

    const float cb = conv_b[0];
    float2 r0 = k2_finish(sc0, scs, cb);   // q0,q1
    float2 r1 = k2_finish(sc1, scs, cb);   // q2,q3
    float4 o4 = make_float4(r0.x, r0.y, r1.x, r1.y);
    *reinterpret_cast<float4*>(&g_wctx2[b*QL + q0]) = o4;
}

// ---------------------------------------------------------------------------
// k3: split-K FC partials. grid (64 splits, 7 a-groups). Each warp handles
// an a-pair; lane = batch. Deterministic (no atomics).
// ---------------------------------------------------------------------------
__global__ void __launch_bounds__(256) k3_fc(const float* __restrict__ fcw){
    const int split = blockIdx.x;
    const int k0    = split * KCH;
    const int tid   = threadIdx.x;
    const int lane  = tid & 31;
    const int w     = tid >> 5;

    __shared__ float sm[KCH*33];   // [k][b], padded (33.8 KB)
    for (int idx = tid; idx < BB*KCH; idx += 256){
        int b = idx >> 8;          // /256
        int k = idx & 255;
        sm[k*33 + b] = g_wctx2[b*QL + k0 + k];
    }
    __syncthreads();

    const int a0 = blockIdx.y * 16 + w * 2;   // a-pair {a0, a0+1}
    if (a0 >= ADIM) return;

    const float4* f0 = reinterpret_cast<const float4*>(fcw + (long long)(a0  )*QL + k0);
    const float4* f1 = reinterpret_cast<const float4*>(fcw + (long long)(a0+1)*QL + k0);
    float acc0 = 0.f, acc1 = 0.f;
    #pragma unroll 8
    for (int kq = 0; kq < KCH/4; ++kq){
        float4 x0 = __ldg(f0 + kq);
        float4 x1 = __ldg(f1 + kq);
        const int k = kq*4;
        float v0 = sm[(k+0)*33 + lane];
        float v1 = sm[(k+1)*33 + lane];
        float v2 = sm[(k+2)*33 + lane];
        float v3 = sm[(k+3)*33 + lane];
        acc0 = fmaf(x0.x, v0, acc0);  acc1 = fmaf(x1.x, v0, acc1);
        acc0 = fmaf(x0.y, v1, acc0);  acc1 = fmaf(x1.y, v1, acc1);
        acc0 = fmaf(x0.z, v2, acc0);  acc1 = fmaf(x1.z, v2, acc1);
        acc0 = fmaf(x0.w, v3, acc0);  acc1 = fmaf(x1.w, v3, acc1);
    }
    g_partial[split*(ADIM*BB) + (a0  )*BB + lane] = acc0;
    g_partial[split*(ADIM*BB) + (a0+1)*BB + lane] = acc1;
}

// ---------------------------------------------------------------------------
// k4: parallel reduce of split partials. One block per a-column.
// ---------------------------------------------------------------------------
__global__ void __launch_bounds__(256) k4_reduce(const float* __restrict__ fcb,
                                                 float* __restrict__ out){
    const int a   = blockIdx.x;          // 0..99
    const int tid = threadIdx.x;
    const int b   = tid & 31;
    const int g   = tid >> 5;            // 0..7

    float acc = 0.f;
    #pragma unroll
    for (int sp = g; sp < NSPLIT; sp += 8)
        acc += g_partial[sp*(ADIM*BB) + a*BB + b];

    __shared__ float red[256];
    red[tid] = acc;
    __syncthreads();
    if (g == 0){
        float v = red[b] + red[b+32] + red[b+64] + red[b+96]
                + red[b+128] + red[b+160] + red[b+192] + red[b+224];
        out[b*ADIM + a] = v + fcb[a];
    }
}

extern "C" void kernel_launch(void* const* d_in, const int* in_sizes, int n_in,
                              void* d_out, int out_size){
    const float* inputs     = (const float*)d_in[0];  // [32,64,128,128]
    const float* context    = (const float*)d_in[1];  // [32,768,18]
    const float* conv_ctx_w = (const float*)d_in[2];  // [64,768]
    const float* conv_w     = (const float*)d_in[3];  // [64]
    const float* conv_b     = (const float*)d_in[4];  // [1]
    const float* fc_w       = (const float*)d_in[5];  // [100,16384]
    const float* fc_b       = (const float*)d_in[6];  // [100]
    float* out = (float*)d_out;                        // [32,100]

    k1_sourceT<<<dim3(8, BB), 256>>>(context, conv_ctx_w);
    k2_attn   <<<dim3(QL/1024, BB), 256>>>(inputs, conv_w, conv_b);
    k3_fc     <<<dim3(NSPLIT, 7), 256>>>(fc_w);
    k4_reduce <<<ADIM, 256>>>(fc_b, out);
}